// round 14
// baseline (speedup 1.0000x reference)
#include <cuda_runtime.h>

#define SEQL   2048
#define BATCH  2
#define DMODEL 1024
#define NHEAD  16
#define DK     64
#define NT     (SEQL*BATCH)      // 4096 token rows
#define BH     (BATCH*NHEAD)     // 32
#define QSCALE 0.125f            // DK^-0.5

// Scratch (static device globals — no runtime allocation allowed)
// tf32-converted inputs/weights
__device__ unsigned g_qin[NT*DMODEL], g_kin[NT*DMODEL], g_vin[NT*DMODEL];
__device__ unsigned g_wq[DMODEL*DMODEL], g_wk[DMODEL*DMODEL];
__device__ unsigned g_wv[DMODEL*DMODEL], g_wo[DMODEL*DMODEL];
// projected Q/K/V (tf32 bits) and attention output (tf32 bits)
__device__ unsigned g_q[BH*SEQL*DK];    // [bh][l][dk]
__device__ unsigned g_k[BH*SEQL*DK];    // [bh][s][dk]
__device__ unsigned g_v[BH*SEQL*DK];    // [bh][s][dk]
__device__ unsigned g_attn[NT*DMODEL];  // merged heads [t][d]

// ---------------------------------------------------------------------------
// helpers
// ---------------------------------------------------------------------------
__device__ __forceinline__ unsigned f2tf(float x) {
    unsigned r;
    asm("cvt.rna.tf32.f32 %0, %1;" : "=r"(r) : "f"(x));
    return r;
}

__device__ __forceinline__ void cp16(unsigned saddr, const void* gaddr) {
    asm volatile("cp.async.cg.shared.global [%0], [%1], 16;"
                 :: "r"(saddr), "l"(gaddr));
}
__device__ __forceinline__ void cp_commit() {
    asm volatile("cp.async.commit_group;");
}
template<int N>
__device__ __forceinline__ void cp_wait() {
    asm volatile("cp.async.wait_group %0;" :: "n"(N));
}

// D += A*B, m16n8k8 tf32 (A row-major frag, B col-major frag, f32 accum)
__device__ __forceinline__ void mma8(float c[4], const unsigned a[4],
                                     unsigned b0, unsigned b1) {
    asm("mma.sync.aligned.m16n8k8.row.col.f32.tf32.tf32.f32 "
        "{%0,%1,%2,%3},{%4,%5,%6,%7},{%8,%9},{%0,%1,%2,%3};"
        : "+f"(c[0]), "+f"(c[1]), "+f"(c[2]), "+f"(c[3])
        : "r"(a[0]), "r"(a[1]), "r"(a[2]), "r"(a[3]), "r"(b0), "r"(b1));
}

// ---------------------------------------------------------------------------
// One-shot tf32 conversion of inputs + weights (HBM-streaming, ~16us)
// z: 0..2 -> query/key/value (NT*DMODEL), 3..6 -> WQ/WK/WV/WO (DMODEL*DMODEL)
// ---------------------------------------------------------------------------
__global__ void __launch_bounds__(256) cvt_inputs(
    const float* __restrict__ q, const float* __restrict__ k,
    const float* __restrict__ v,
    const float* __restrict__ wq, const float* __restrict__ wk,
    const float* __restrict__ wv, const float* __restrict__ wo,
    unsigned* __restrict__ oq, unsigned* __restrict__ ok,
    unsigned* __restrict__ ov,
    unsigned* __restrict__ owq, unsigned* __restrict__ owk,
    unsigned* __restrict__ owv, unsigned* __restrict__ owo)
{
    const float* src; unsigned* dst; int n;
    switch (blockIdx.z) {
        case 0: src = q;  dst = oq;  n = NT*DMODEL;     break;
        case 1: src = k;  dst = ok;  n = NT*DMODEL;     break;
        case 2: src = v;  dst = ov;  n = NT*DMODEL;     break;
        case 3: src = wq; dst = owq; n = DMODEL*DMODEL; break;
        case 4: src = wk; dst = owk; n = DMODEL*DMODEL; break;
        case 5: src = wv; dst = owv; n = DMODEL*DMODEL; break;
        default: src = wo; dst = owo; n = DMODEL*DMODEL; break;
    }
    int stride = gridDim.x * blockDim.x;
    for (int i = blockIdx.x * blockDim.x + threadIdx.x; 4*i < n; i += stride) {
        float4 t = *(const float4*)(src + 4*i);
        *(uint4*)(dst + 4*i) =
            make_uint4(f2tf(t.x), f2tf(t.y), f2tf(t.z), f2tf(t.w));
    }
}

// ---------------------------------------------------------------------------
// TF32 GEMM v3: val[t][d] = (sum_i A[t][i]*W[d][i] + bias[d]) * scale
// A, W already tf32 bits. cp.async double-buffered smem pipeline (no register
// staging, no in-loop cvt). Block tile 128(m) x 256(n), 8 warps in 2x4 grid,
// warp tile 64x64 (4 m-tiles x 8 n-tiles).
// MODE 1: store tf32 head-split natural [bh][l/s][dk]   (Q, K, V)
// MODE 2: store f32 plain               [t][d]          (final output)
// smem stride 36 (36 mod 32 == 4 -> fragment patterns conflict-free;
// 36 elems = 144 B, 16B-aligned for cp.async)
// ---------------------------------------------------------------------------
#define GSTAGE (128*36 + 256*36)   // words per pipeline stage

template<int MODE>
__device__ __forceinline__ void gemm_body(const unsigned* __restrict__ A,
                                          const unsigned* __restrict__ W,
                                          const float* __restrict__ bias,
                                          unsigned* __restrict__ out,
                                          float scale)
{
    extern __shared__ unsigned gsm[];

    const int tid  = threadIdx.x;
    const int lane = tid & 31;
    const int w    = tid >> 5;
    const int wm   = w >> 2;        // 0..1 -> m offset 64*wm
    const int wn   = w & 3;         // 0..3 -> n offset 64*wn
    const int t0   = blockIdx.y * 128;
    const int d0   = blockIdx.x * 256;

    const unsigned sbase = (unsigned)__cvta_generic_to_shared(gsm);

    float acc[4][8][4] = {};

    // issue async copy of k-chunk kc into stage stg
    auto copy_chunk = [&](int stg, int kc) {
        unsigned sb = sbase + stg * (GSTAGE * 4);
        #pragma unroll
        for (int i = 0; i < 4; i++) {
            int f = tid + i * 256;          // A: 128 rows x 8 float4
            int r = f >> 3, c4 = (f & 7) << 2;
            cp16(sb + (r*36 + c4)*4, A + (long)(t0 + r)*DMODEL + kc + c4);
        }
        #pragma unroll
        for (int i = 0; i < 8; i++) {
            int f = tid + i * 256;          // W: 256 rows x 8 float4
            int r = f >> 3, c4 = (f & 7) << 2;
            cp16(sb + (128*36 + r*36 + c4)*4,
                 W + (long)(d0 + r)*DMODEL + kc + c4);
        }
        cp_commit();
    };
    // consume stage stg (32 k-steps)
    auto mma_chunk = [&](int stg) {
        unsigned* As = gsm + stg * GSTAGE;
        unsigned* Ws = As + 128*36;
        #pragma unroll
        for (int k0 = 0; k0 < 32; k0 += 8) {
            unsigned a[4][4];
            #pragma unroll
            for (int mt = 0; mt < 4; mt++) {
                int rb = (64*wm + 16*mt + (lane >> 2)) * 36 + k0 + (lane & 3);
                a[mt][0] = As[rb];
                a[mt][1] = As[rb + 8*36];
                a[mt][2] = As[rb + 4];
                a[mt][3] = As[rb + 8*36 + 4];
            }
            #pragma unroll
            for (int nt = 0; nt < 8; nt++) {
                int nb = (64*wn + 8*nt + (lane >> 2)) * 36 + k0 + (lane & 3);
                unsigned b0 = Ws[nb], b1 = Ws[nb + 4];
                #pragma unroll
                for (int mt = 0; mt < 4; mt++)
                    mma8(acc[mt][nt], a[mt], b0, b1);
            }
        }
    };

    const int NCH = DMODEL / 32;   // 32 chunks
    copy_chunk(0, 0);
    for (int c = 0; c < NCH; c++) {
        if (c + 1 < NCH) {
            copy_chunk((c + 1) & 1, (c + 1) * 32);
            cp_wait<1>();
        } else {
            cp_wait<0>();
        }
        __syncthreads();
        mma_chunk(c & 1);
        __syncthreads();   // reads done before this buffer is refilled
    }

    // Epilogue: c0:(r,c) c1:(r,c+1) c2:(r+8,c) c3:(r+8,c+1)
    #pragma unroll
    for (int mt = 0; mt < 4; mt++) {
        #pragma unroll
        for (int nt = 0; nt < 8; nt++) {
            int row = t0 + 64*wm + 16*mt + (lane >> 2);
            int col = d0 + 64*wn + 8*nt + 2*(lane & 3);
            float bv0 = bias[col], bv1 = bias[col + 1];
            float v00 = (acc[mt][nt][0] + bv0) * scale;
            float v01 = (acc[mt][nt][1] + bv1) * scale;
            float v10 = (acc[mt][nt][2] + bv0) * scale;
            float v11 = (acc[mt][nt][3] + bv1) * scale;
            if (MODE == 1) {
                // store tf32 bits, head-split natural layout
                int l0_ = row >> 1, b0_ = row & 1;
                int h = col >> 6, dk = col & 63;
                long i0 = (((long)(b0_*NHEAD + h))*SEQL + l0_)*DK + dk;
                *(uint2*)&out[i0] = make_uint2(f2tf(v00), f2tf(v01));
                int l1_ = (row + 8) >> 1, b1_ = (row + 8) & 1;
                long i1 = (((long)(b1_*NHEAD + h))*SEQL + l1_)*DK + dk;
                *(uint2*)&out[i1] = make_uint2(f2tf(v10), f2tf(v11));
            } else {
                // store f32 bits, plain layout
                *(uint2*)&out[(long)row*DMODEL + col] =
                    make_uint2(__float_as_uint(v00), __float_as_uint(v01));
                *(uint2*)&out[(long)(row+8)*DMODEL + col] =
                    make_uint2(__float_as_uint(v10), __float_as_uint(v11));
            }
        }
    }
}

// Fused Q/K/V projections: blockIdx.z selects the stream.
__global__ void __launch_bounds__(256, 1) gemm_qkv(
    const unsigned* __restrict__ Aq, const unsigned* __restrict__ Ak,
    const unsigned* __restrict__ Av,
    const unsigned* __restrict__ Wq, const unsigned* __restrict__ Wk,
    const unsigned* __restrict__ Wv,
    const float* __restrict__ bq, const float* __restrict__ bk,
    const float* __restrict__ bv,
    unsigned* __restrict__ oq, unsigned* __restrict__ ok,
    unsigned* __restrict__ ov)
{
    if (blockIdx.z == 0)      gemm_body<1>(Aq, Wq, bq, oq, QSCALE);
    else if (blockIdx.z == 1) gemm_body<1>(Ak, Wk, bk, ok, 1.0f);
    else                      gemm_body<1>(Av, Wv, bv, ov, 1.0f);
}

__global__ void __launch_bounds__(256, 1) gemm_o(const unsigned* __restrict__ A,
                                                 const unsigned* __restrict__ W,
                                                 const float* __restrict__ bias,
                                                 unsigned* __restrict__ out)
{
    gemm_body<2>(A, W, bias, out, 1.0f);
}

// ---------------------------------------------------------------------------
// TF32 flash attention v2b. One block = 256 query rows for one (b,h).
// Q/K/V arrive as tf32 bits -> smem loads are plain uint4 copies (no cvt).
// Output written as tf32 bits for gemm_o.
// ---------------------------------------------------------------------------
__global__ void __launch_bounds__(256, 1) flash_tc(const unsigned* __restrict__ q,
                                                   const unsigned* __restrict__ k,
                                                   const unsigned* __restrict__ v,
                                                   unsigned* __restrict__ outm)
{
    extern __shared__ unsigned sm[];
    unsigned* Qs = sm;                  // [256][68]
    unsigned* Ks = Qs + 256*68;         // [128][68]
    unsigned* Vs = Ks + 128*68;         // [128][72]
    unsigned* Ps = Vs + 128*72;         // [256][68] (64 cols used per half)

    const int tid  = threadIdx.x;
    const int lane = tid & 31;
    const int w    = tid >> 5;
    const int bh   = blockIdx.y;
    const int lblk = blockIdx.x * 256;

    const unsigned* qb = q + ((long)bh * SEQL + lblk) * DK;
    const unsigned* kb = k + (long)bh * SEQL * DK;
    const unsigned* vb = v + (long)bh * SEQL * DK;

    // Load Q tile once (256 x 64)
    #pragma unroll
    for (int i = 0; i < 16; i++) {
        int f  = tid + i * 256;
        int r  = f >> 4;
        int c4 = (f & 15) << 2;
        *(uint4*)&Qs[r*68 + c4] = *(const uint4*)(qb + (long)r*DK + c4);
    }

    float o[2][8][4] = {};
    float mr[2][2], lr[2][2];
    mr[0][0] = mr[0][1] = mr[1][0] = mr[1][1] = -1e30f;
    lr[0][0] = lr[0][1] = lr[1][0] = lr[1][1] = 0.f;

    for (int s0 = 0; s0 < SEQL; s0 += 128) {
        // Load K, V chunk (128 x 64 each)
        #pragma unroll
        for (int i = 0; i < 8; i++) {
            int f  = tid + i * 256;
            int r  = f >> 4;
            int c4 = (f & 15) << 2;
            *(uint4*)&Ks[r*68 + c4] = *(const uint4*)(kb + (long)(s0 + r)*DK + c4);
            *(uint4*)&Vs[r*72 + c4] = *(const uint4*)(vb + (long)(s0 + r)*DK + c4);
        }
        __syncthreads();

        #pragma unroll 1
        for (int hh = 0; hh < 2; hh++) {       // 64-col s-halves
            // S = Q * K_half^T : warp tile 32 x 64, contract dk=64
            float s[2][8][4] = {};
            #pragma unroll
            for (int k0 = 0; k0 < 64; k0 += 8) {
                unsigned a[2][4];
                #pragma unroll
                for (int mt = 0; mt < 2; mt++) {
                    int rb = (32*w + 16*mt + (lane >> 2)) * 68 + k0 + (lane & 3);
                    a[mt][0] = Qs[rb];
                    a[mt][1] = Qs[rb + 8*68];
                    a[mt][2] = Qs[rb + 4];
                    a[mt][3] = Qs[rb + 8*68 + 4];
                }
                #pragma unroll
                for (int nt = 0; nt < 8; nt++) {
                    int nb = (64*hh + 8*nt + (lane >> 2)) * 68 + k0 + (lane & 3);
                    unsigned b0 = Ks[nb], b1 = Ks[nb + 4];
                    mma8(s[0][nt], a[0], b0, b1);
                    mma8(s[1][nt], a[1], b0, b1);
                }
            }

            // Online softmax + P staging, per m-tile
            #pragma unroll
            for (int mt = 0; mt < 2; mt++) {
                float mx0 = -1e30f, mx1 = -1e30f;
                #pragma unroll
                for (int nt = 0; nt < 8; nt++) {
                    mx0 = fmaxf(mx0, fmaxf(s[mt][nt][0], s[mt][nt][1]));
                    mx1 = fmaxf(mx1, fmaxf(s[mt][nt][2], s[mt][nt][3]));
                }
                mx0 = fmaxf(mx0, __shfl_xor_sync(0xffffffffu, mx0, 1));
                mx0 = fmaxf(mx0, __shfl_xor_sync(0xffffffffu, mx0, 2));
                mx1 = fmaxf(mx1, __shfl_xor_sync(0xffffffffu, mx1, 1));
                mx1 = fmaxf(mx1, __shfl_xor_sync(0xffffffffu, mx1, 2));
                float nm0 = fmaxf(mr[mt][0], mx0), nm1 = fmaxf(mr[mt][1], mx1);
                float al0 = __expf(mr[mt][0] - nm0), al1 = __expf(mr[mt][1] - nm1);
                mr[mt][0] = nm0; mr[mt][1] = nm1;
                float su0 = 0.f, su1 = 0.f;
                #pragma unroll
                for (int nt = 0; nt < 8; nt++) {
                    s[mt][nt][0] = __expf(s[mt][nt][0] - nm0);
                    s[mt][nt][1] = __expf(s[mt][nt][1] - nm0);
                    s[mt][nt][2] = __expf(s[mt][nt][2] - nm1);
                    s[mt][nt][3] = __expf(s[mt][nt][3] - nm1);
                    su0 += s[mt][nt][0] + s[mt][nt][1];
                    su1 += s[mt][nt][2] + s[mt][nt][3];
                }
                su0 += __shfl_xor_sync(0xffffffffu, su0, 1);
                su0 += __shfl_xor_sync(0xffffffffu, su0, 2);
                su1 += __shfl_xor_sync(0xffffffffu, su1, 1);
                su1 += __shfl_xor_sync(0xffffffffu, su1, 2);
                lr[mt][0] = lr[mt][0] * al0 + su0;
                lr[mt][1] = lr[mt][1] * al1 + su1;
                #pragma unroll
                for (int nt = 0; nt < 8; nt++) {
                    o[mt][nt][0] *= al0; o[mt][nt][1] *= al0;
                    o[mt][nt][2] *= al1; o[mt][nt][3] *= al1;
                }
                // stage P-half (tf32) into warp-private smem rows
                int pr0 = (32*w + 16*mt + (lane >> 2)) * 68;
                int pr1 = pr0 + 8*68;
                #pragma unroll
                for (int nt = 0; nt < 8; nt++) {
                    int pc = 8*nt + 2*(lane & 3);
                    *(uint2*)&Ps[pr0 + pc] =
                        make_uint2(f2tf(s[mt][nt][0]), f2tf(s[mt][nt][1]));
                    *(uint2*)&Ps[pr1 + pc] =
                        make_uint2(f2tf(s[mt][nt][2]), f2tf(s[mt][nt][3]));
                }
            }
            __syncwarp();

            // O += P_half * V_half : warp tile 32 x 64, contract s=64
            #pragma unroll
            for (int k0 = 0; k0 < 64; k0 += 8) {
                unsigned a[2][4];
                #pragma unroll
                for (int mt = 0; mt < 2; mt++) {
                    int rb = (32*w + 16*mt + (lane >> 2)) * 68 + k0 + (lane & 3);
                    a[mt][0] = Ps[rb];
                    a[mt][1] = Ps[rb + 8*68];
                    a[mt][2] = Ps[rb + 4];
                    a[mt][3] = Ps[rb + 8*68 + 4];
                }
                #pragma unroll
                for (int nt = 0; nt < 8; nt++) {
                    int nb = (64*hh + k0 + (lane & 3)) * 72 + 8*nt + (lane >> 2);
                    unsigned b0 = Vs[nb], b1 = Vs[nb + 4*72];
                    mma8(o[0][nt], a[0], b0, b1);
                    mma8(o[1][nt], a[1], b0, b1);
                }
            }
            __syncwarp();   // Ps reads done before next half restages
        }
        __syncthreads();    // Ks/Vs consumed before next chunk overwrites
    }

    // Epilogue: merged heads attn[(l*B + b)*D + h*64 + dk], tf32 bits
    const int b = bh >> 4, h = bh & 15;
    #pragma unroll
    for (int mt = 0; mt < 2; mt++) {
        float inv0 = 1.f / lr[mt][0], inv1 = 1.f / lr[mt][1];
        int lrow = lblk + 32*w + 16*mt + (lane >> 2);
        #pragma unroll
        for (int nt = 0; nt < 8; nt++) {
            int d = h*DK + 8*nt + 2*(lane & 3);
            *(uint2*)&outm[((long)lrow*BATCH + b)*DMODEL + d] =
                make_uint2(f2tf(o[mt][nt][0]*inv0), f2tf(o[mt][nt][1]*inv0));
            *(uint2*)&outm[((long)(lrow+8)*BATCH + b)*DMODEL + d] =
                make_uint2(f2tf(o[mt][nt][2]*inv1), f2tf(o[mt][nt][3]*inv1));
        }
    }
}

// ---------------------------------------------------------------------------
extern "C" void kernel_launch(void* const* d_in, const int* in_sizes, int n_in,
                              void* d_out, int out_size)
{
    const float* query = (const float*)d_in[0];
    const float* key   = (const float*)d_in[1];
    const float* value = (const float*)d_in[2];
    const float* WQ  = (const float*)d_in[3];
    const float* WQb = (const float*)d_in[4];
    const float* WK  = (const float*)d_in[5];
    const float* WKb = (const float*)d_in[6];
    const float* WV  = (const float*)d_in[7];
    const float* WVb = (const float*)d_in[8];
    const float* WO  = (const float*)d_in[9];
    const float* WOb = (const float*)d_in[10];
    unsigned* out = (unsigned*)d_out;   // f32 bits stored via uint2

    unsigned *qin, *kin, *vin, *wq, *wk, *wv, *wo;
    unsigned *qN, *kN, *vN, *attn;
    cudaGetSymbolAddress((void**)&qin,  g_qin);
    cudaGetSymbolAddress((void**)&kin,  g_kin);
    cudaGetSymbolAddress((void**)&vin,  g_vin);
    cudaGetSymbolAddress((void**)&wq,   g_wq);
    cudaGetSymbolAddress((void**)&wk,   g_wk);
    cudaGetSymbolAddress((void**)&wv,   g_wv);
    cudaGetSymbolAddress((void**)&wo,   g_wo);
    cudaGetSymbolAddress((void**)&qN,   g_q);
    cudaGetSymbolAddress((void**)&kN,   g_k);
    cudaGetSymbolAddress((void**)&vN,   g_v);
    cudaGetSymbolAddress((void**)&attn, g_attn);

    const int gemm_smem  = 2 * GSTAGE * 4;                           // 110592 B
    const int flash_smem = (256*68 + 128*68 + 128*72 + 256*68) * 4;  // 210944 B
    cudaFuncSetAttribute(gemm_qkv, cudaFuncAttributeMaxDynamicSharedMemorySize,
                         gemm_smem);
    cudaFuncSetAttribute(gemm_o, cudaFuncAttributeMaxDynamicSharedMemorySize,
                         gemm_smem);
    cudaFuncSetAttribute(flash_tc, cudaFuncAttributeMaxDynamicSharedMemorySize,
                         flash_smem);

    dim3 blk(256);

    // One-shot tf32 conversion of all GEMM operands
    cvt_inputs<<<dim3(512, 1, 7), blk>>>(query, key, value, WQ, WK, WV, WO,
                                         qin, kin, vin, wq, wk, wv, wo);

    // Fused Q/K/V projections (z selects stream); block tile 128m x 256n
    gemm_qkv<<<dim3(DMODEL/256, NT/128, 3), blk, gemm_smem>>>(
        qin, kin, vin, wq, wk, wv, WQb, WKb, WVb, qN, kN, vN);

    flash_tc<<<dim3(SEQL/256, BH), blk, flash_smem>>>(qN, kN, vN, attn);

    gemm_o<<<dim3(DMODEL/256, NT/128), blk, gemm_smem>>>(attn, wo, WOb, out);
}